// round 14
// baseline (speedup 1.0000x reference)
#include <cuda_runtime.h>
#include <cuda_bf16.h>
#include <cstdint>

// Problem constants
#define BV 8
#define NV 4096
#define DV 256
#define HIDV 1024
#define LV 6
#define MV (BV*NV)          // 32768 rows
#define NSM 148
#define PGRID (2*NSM)       // persistent grid: 2 CTAs/SM

// ---------------------------------------------------------------------------
// Scratch (static __device__ — no allocation allowed)
// H lives in PERM layout: perm row i<cnt is the target whose winner slot is i
// (so the GRU's gi operand is msgs_compact[i] — identity, dense);
// loser targets occupy perm rows [cnt, MV).
// ---------------------------------------------------------------------------
__device__ __nv_bfloat16 g_H0[(size_t)MV*DV];          // 16 MB  (perm layout)
__device__ __nv_bfloat16 g_H1[(size_t)MV*DV];          // 16 MB  (perm layout)
__device__ __nv_bfloat16 g_hid[(size_t)MV*HIDV];       // 64 MB  (compact rows)
__device__ __nv_bfloat16 g_msgs[(size_t)(MV+8)*DV];    // 16 MB  (+ zero row at MV)
__device__ __nv_bfloat16 g_rz[(size_t)MV*512];         // 32 MB  (perm-dense)
__device__ __nv_bfloat16 g_embf[NV*DV];                // 2 MB   (bf16 emb, L0 MLP)
__device__ int   g_win[MV];     // target row -> winning in-batch source index or -1
__device__ int   g_rows[MV];    // slot -> global source row (natural)
__device__ int   g_rowsP[MV];   // slot -> source row in PERM space (hid A gather)
__device__ int   g_perm[MV];    // perm row -> target row
__device__ int   g_invp[MV];    // target row -> perm row
__device__ int   g_a1idx[MV];   // perm row -> msgs row (identity <cnt, else MV)
__device__ int   g_a1idx0[MV];  // L0 variant: perm row -> shared msgs row or MV
__device__ int   g_cnt;         // winner count
__device__ int   g_lcnt;        // loser count
__device__ __nv_bfloat16 g_W1[HIDV*DV];
__device__ __nv_bfloat16 g_W2[DV*HIDV];
__device__ __nv_bfloat16 g_Wih[3*DV*DV];
__device__ __nv_bfloat16 g_Whh[3*DV*DV];
__device__ float g_brz[2*DV];
__device__ float g_comb[BV*DV];

// ---------------------------------------------------------------------------
// Helpers
// ---------------------------------------------------------------------------
__device__ __forceinline__ float geluf(float x) {
    return 0.5f * x * (1.0f + erff(x * 0.7071067811865476f));
}
__device__ __forceinline__ float sigmf(float x) {
    return 1.0f / (1.0f + __expf(-x));
}
__device__ __forceinline__ void cpasync16(uint32_t dst, const void* src) {
    asm volatile("cp.async.cg.shared.global [%0], [%1], 16;\n" :: "r"(dst), "l"(src));
}
__device__ __forceinline__ void ldsm_x4(unsigned r[4], uint32_t addr) {
    asm volatile("ldmatrix.sync.aligned.m8n8.x4.shared.b16 {%0,%1,%2,%3}, [%4];\n"
                 : "=r"(r[0]), "=r"(r[1]), "=r"(r[2]), "=r"(r[3]) : "r"(addr));
}
__device__ __forceinline__ void mma_bf16(float c[4], const unsigned a[4], const unsigned b[2]) {
    asm volatile(
        "mma.sync.aligned.m16n8k16.row.col.f32.bf16.bf16.f32 "
        "{%0,%1,%2,%3}, {%4,%5,%6,%7}, {%8,%9}, {%0,%1,%2,%3};\n"
        : "+f"(c[0]), "+f"(c[1]), "+f"(c[2]), "+f"(c[3])
        : "r"(a[0]), "r"(a[1]), "r"(a[2]), "r"(a[3]), "r"(b[0]), "r"(b[1]));
}

// ---------------------------------------------------------------------------
// Prep (merged: weight rounding + bf16 emb copy + winner-table init)
// ---------------------------------------------------------------------------
__global__ void k_prep(const float* __restrict__ W1, const float* __restrict__ W2,
                       const float* __restrict__ Wih, const float* __restrict__ Whh,
                       const float* __restrict__ bih, const float* __restrict__ bhh,
                       const float* __restrict__ emb) {
    int i = blockIdx.x * 256 + threadIdx.x;           // grid covers HIDV*DV = 262144
    if (i < HIDV*DV) { g_W1[i] = __float2bfloat16_rn(W1[i]); g_W2[i] = __float2bfloat16_rn(W2[i]); }
    if (i < 3*DV*DV) { g_Wih[i] = __float2bfloat16_rn(Wih[i]); g_Whh[i] = __float2bfloat16_rn(Whh[i]); }
    if (i < 2*DV)    { g_brz[i] = bih[i] + bhh[i]; }
    if (i < NV*DV/8) {
        size_t base = (size_t)i * 8;
        float4 a = *reinterpret_cast<const float4*>(emb + base);
        float4 b = *reinterpret_cast<const float4*>(emb + base + 4);
        __nv_bfloat162 o[4];
        o[0].x = __float2bfloat16_rn(a.x); o[0].y = __float2bfloat16_rn(a.y);
        o[1].x = __float2bfloat16_rn(a.z); o[1].y = __float2bfloat16_rn(a.w);
        o[2].x = __float2bfloat16_rn(b.x); o[2].y = __float2bfloat16_rn(b.y);
        o[3].x = __float2bfloat16_rn(b.z); o[3].y = __float2bfloat16_rn(b.w);
        *reinterpret_cast<uint4*>(g_embf + base) = *reinterpret_cast<uint4*>(o);
    }
    if (i < MV) {
        g_win[i] = -1;
        g_rows[i] = 0;
        g_rowsP[i] = 0;
        g_perm[i] = 0;
        g_invp[i] = 0;
        g_a1idx[i]  = MV;                             // default: zero msgs row
        g_a1idx0[i] = MV;
    }
    if (i < DV) g_msgs[(size_t)MV*DV + i] = __float2bfloat16_rn(0.f);
    if (i == 0) { g_cnt = 0; g_lcnt = 0; }
}

__global__ void k_win_fill(const int* __restrict__ p) {
    int i = blockIdx.x * 256 + threadIdx.x;           // MV
    int b = i >> 12, t = i & 4095;
    atomicMax(&g_win[(b << 12) + p[i]], t);
}
// Permutation build. Slot order is replay-dependent but output-invariant:
// every consumer indexes through the tables and rows are independent.
__global__ void k_compact() {
    int t = blockIdx.x * 256 + threadIdx.x;           // MV target rows
    int w = g_win[t];
    if (w >= 0) {
        int slot = atomicAdd(&g_cnt, 1);
        int src = ((t >> 12) << 12) | w;
        g_rows[slot]   = src;
        g_perm[slot]   = t;
        g_invp[t]      = slot;
        g_a1idx[slot]  = slot;      // identity: msgs compact
        g_a1idx0[slot] = w;         // L0: msgs shared across batch
    } else {
        int l = atomicAdd(&g_lcnt, 1);
        g_perm[MV - 1 - l] = t;
        g_invp[t] = MV - 1 - l;
    }
}
// Hp init (perm layout) from emb + rowsP composition (merged compact2).
__global__ void k_h0p(const float* __restrict__ emb) {
    int idx = blockIdx.x * 256 + threadIdx.x;         // MV*32 chunks of 8 elems
    if (idx < MV && idx < g_cnt) g_rowsP[idx] = g_invp[g_rows[idx]];
    int i  = idx >> 5;
    int c8 = idx & 31;
    int er = g_perm[i] & (NV - 1);
    const float* s = emb + (size_t)er * DV + c8 * 8;
    float4 a = *reinterpret_cast<const float4*>(s);
    float4 b = *reinterpret_cast<const float4*>(s + 4);
    __nv_bfloat162 o[4];
    o[0].x = __float2bfloat16_rn(a.x); o[0].y = __float2bfloat16_rn(a.y);
    o[1].x = __float2bfloat16_rn(a.z); o[1].y = __float2bfloat16_rn(a.w);
    o[2].x = __float2bfloat16_rn(b.x); o[2].y = __float2bfloat16_rn(b.y);
    o[3].x = __float2bfloat16_rn(b.z); o[3].y = __float2bfloat16_rn(b.w);
    *reinterpret_cast<uint4*>(g_H0 + (size_t)i * DV + c8 * 8) = *reinterpret_cast<uint4*>(o);
}

// ---------------------------------------------------------------------------
// Persistent BF16 GEMM: grid = PGRID blocks, each loops over (row,col) tiles.
// BMx128 tile, KC=32, 4-stage cp.async pipeline, TWO k-tiles per sync.
//   MODE 0: C = bf16(gelu(A1@Wa^T + biasA))                (hid)
//   MODE 1: C = bf16(A1@Wa^T + biasA)                      (msgs)
//   MODE 2: C = bf16(sigmoid(A1@Wa^T + A2@Wb^T + biasA))   (rz; perm-dense)
//   MODE 3: GRU n-gate + state update, dual accumulators   (Hn; perm-dense)
// GATHER: A1 rows indirected through tblA1 (rowsP / a1idx).
// exitMode: 0 dense Mrows; 1 row tiles limited to ceil(cnt/BM);
//           3 dense, but tiles with rowB >= cnt run with nk1=0 (skip gi).
// All NK values (8/16/32) are even; nk1 in {0,8} so the MODE-3 accumulator
// switch never straddles a tile pair. Epilogue touches no smem, so the next
// tile's stage-0/1 issues are safe immediately; stages 2/3 are re-issued only
// after that tile's first barrier.
// Smem rows padded to 40 bf16 (80 B stride) => conflict-free ldmatrix.
// ---------------------------------------------------------------------------
template<int BM, bool GATHER>
__device__ __forceinline__ void load_tile(const __nv_bfloat16* __restrict__ Asrc,
                                          const int* __restrict__ tblA,
                                          const __nv_bfloat16* __restrict__ Wsrc,
                                          int lda, int kcol, long rowB, int colB,
                                          uint32_t smBase, int asOff, int bsOff, int tid) {
    #pragma unroll
    for (int i = 0; i < (BM*4)/256; i++) {
        int idx = i*256 + tid; int r = idx >> 2, ck = idx & 3;
        long ar = GATHER ? (long)tblA[rowB + r] : (rowB + r);
        cpasync16(smBase + (unsigned)((asOff + r*40 + ck*8) * 2),
                  Asrc + ar * (long)lda + kcol + ck*8);
    }
    #pragma unroll
    for (int i = 0; i < 2; i++) {
        int idx = i*256 + tid; int r = idx >> 2, ck = idx & 3;
        cpasync16(smBase + (unsigned)((bsOff + r*40 + ck*8) * 2),
                  Wsrc + (long)(colB + r) * lda + kcol + ck*8);
    }
    asm volatile("cp.async.commit_group;\n" ::);
}

template<int MT>
__device__ __forceinline__ void compute_tile(uint32_t aB, uint32_t bB, int lane,
                                             int wr0, int wc0, float acc[][4][4]) {
    #pragma unroll
    for (int kst = 0; kst < 2; kst++) {
        unsigned a[MT][4], b[4][2];
        int arow = wr0 + (lane & 15);
        int acol = kst*16 + (lane >> 4) * 8;
        #pragma unroll
        for (int i = 0; i < MT; i++)
            ldsm_x4(a[i], aB + (unsigned)(((arow + i*16) * 40 + acol) * 2));
        #pragma unroll
        for (int jj = 0; jj < 2; jj++) {
            unsigned t[4];
            int brow = wc0 + jj*16 + (lane & 7) + ((lane >> 4) & 1) * 8;
            int bcol = kst*16 + ((lane >> 3) & 1) * 8;
            ldsm_x4(t, bB + (unsigned)((brow * 40 + bcol) * 2));
            b[jj*2][0]   = t[0]; b[jj*2][1]   = t[1];
            b[jj*2+1][0] = t[2]; b[jj*2+1][1] = t[3];
        }
        #pragma unroll
        for (int i = 0; i < MT; i++)
            #pragma unroll
            for (int j = 0; j < 4; j++)
                mma_bf16(acc[i][j], a[i], b[j]);
    }
}

template<int MODE, int BM, bool GATHER>
__global__ void __launch_bounds__(256)
k_gemm(const __nv_bfloat16* __restrict__ A1, const __nv_bfloat16* __restrict__ A2,
       const __nv_bfloat16* __restrict__ Wa, const __nv_bfloat16* __restrict__ Wb,
       const float* __restrict__ biasA, const float* __restrict__ biasB,
       __nv_bfloat16* __restrict__ C,
       const __nv_bfloat16* __restrict__ rzb, const __nv_bfloat16* __restrict__ Hin,
       const int* __restrict__ tblA1, const int* __restrict__ cntPtr, int exitMode,
       int K1, int K2, int Nout, int Mrows, int tilesY) {
    constexpr int MT = BM / 32;       // warp m-tiles of 16
    extern __shared__ __nv_bfloat16 sm[];
    const int tid = threadIdx.x, lane = tid & 31, warp = tid >> 5;
    const int wr0 = (warp >> 2) * (BM/2), wc0 = (warp & 3) * 32;
    uint32_t smBase = (uint32_t)__cvta_generic_to_shared(sm);
    const int asz = BM * 40, bsz = 128 * 40;      // elements per stage

    const int cnt = (exitMode != 0) ? *cntPtr : 0;
    int rowTiles;
    if (exitMode == 1) rowTiles = (cnt + BM - 1) / BM;
    else               rowTiles = Mrows / BM;
    const int totTiles = rowTiles * tilesY;
    const int NK1F = K1 / 32, NK2 = K2 / 32;

    const int laneR = lane >> 2, laneC = (lane & 3) * 2;

    for (int t = blockIdx.x; t < totTiles; t += gridDim.x) {
        const int rowT = t / tilesY;
        const long rowB = (long)rowT * BM;
        const int  colB = (t - rowT * tilesY) * 128;
        int nk1 = NK1F;
        if (exitMode == 3 && rowB >= cnt) nk1 = 0;
        const int NK = nk1 + NK2;     // always even (8/16/32)

        float acc[MT][4][4];
        float acc2[MT][4][4];
        #pragma unroll
        for (int i = 0; i < MT; i++)
            #pragma unroll
            for (int j = 0; j < 4; j++)
                #pragma unroll
                for (int e = 0; e < 4; e++) {
                    acc[i][j][e] = 0.f;
                    if (MODE == 3) acc2[i][j][e] = 0.f;
                }

        auto issue = [&](int k, int stage) {
            if (k < nk1)
                load_tile<BM, GATHER>(A1, tblA1, Wa, K1, k*32, rowB, colB, smBase,
                                      stage*asz, 4*asz + stage*bsz, tid);
            else
                load_tile<BM, false >(A2, nullptr, Wb, K2, (k - nk1)*32, rowB, colB, smBase,
                                      stage*asz, 4*asz + stage*bsz, tid);
        };

        // Prologue: groups 0,1 in stages 0,1 (stages 0,1 released by the
        // previous tile's last barrier; epilogue uses no smem).
        issue(0, 0); issue(1, 1);

        for (int kt = 0; kt < NK; kt += 2) {
            asm volatile("cp.async.wait_group 0;\n" ::);
            __syncthreads();              // releases stages (kt-2)&3, (kt-1)&3
            if (kt + 2 < NK) issue(kt + 2, (kt + 2) & 3);
            if (kt + 3 < NK) issue(kt + 3, (kt + 3) & 3);
            const int st0 = kt & 3, st1 = (kt + 1) & 3;
            uint32_t aB0 = smBase + (unsigned)((st0 * asz) * 2);
            uint32_t bB0 = smBase + (unsigned)((4*asz + st0 * bsz) * 2);
            uint32_t aB1 = smBase + (unsigned)((st1 * asz) * 2);
            uint32_t bB1 = smBase + (unsigned)((4*asz + st1 * bsz) * 2);
            if (MODE == 3 && kt >= nk1) {
                compute_tile<MT>(aB0, bB0, lane, wr0, wc0, acc2);
                compute_tile<MT>(aB1, bB1, lane, wr0, wc0, acc2);
            } else {
                compute_tile<MT>(aB0, bB0, lane, wr0, wc0, acc);
                compute_tile<MT>(aB1, bB1, lane, wr0, wc0, acc);
            }
        }

        #pragma unroll
        for (int i = 0; i < MT; i++) {
            #pragma unroll
            for (int e = 0; e < 2; e++) {
                long r = rowB + wr0 + i*16 + laneR + e*8;
                #pragma unroll
                for (int j = 0; j < 4; j++) {
                    int c = colB + wc0 + j*8 + laneC;
                    float v0 = acc[i][j][e*2], v1 = acc[i][j][e*2+1];
                    if (MODE == 0) {
                        __nv_bfloat162 o;
                        o.x = __float2bfloat16_rn(geluf(v0 + biasA[c]));
                        o.y = __float2bfloat16_rn(geluf(v1 + biasA[c+1]));
                        *reinterpret_cast<__nv_bfloat162*>(C + r*Nout + c) = o;
                    } else if (MODE == 1) {
                        __nv_bfloat162 o;
                        o.x = __float2bfloat16_rn(v0 + biasA[c]);
                        o.y = __float2bfloat16_rn(v1 + biasA[c+1]);
                        *reinterpret_cast<__nv_bfloat162*>(C + r*Nout + c) = o;
                    } else if (MODE == 2) {
                        __nv_bfloat162 o;
                        o.x = __float2bfloat16_rn(sigmf(v0 + biasA[c]));
                        o.y = __float2bfloat16_rn(sigmf(v1 + biasA[c+1]));
                        *reinterpret_cast<__nv_bfloat162*>(C + r*Nout + c) = o;
                    } else {
                        // i-gate half = acc (zero for loser tiles, nk1=0)
                        float i0 = v0 + biasA[c],            i1 = v1 + biasA[c+1];
                        float h0 = acc2[i][j][e*2] + biasB[c];
                        float h1 = acc2[i][j][e*2+1] + biasB[c+1];
                        float2 rr = __bfloat1622float2(*reinterpret_cast<const __nv_bfloat162*>(rzb + r*512 + c));
                        float2 zz = __bfloat1622float2(*reinterpret_cast<const __nv_bfloat162*>(rzb + r*512 + 256 + c));
                        float2 hh = __bfloat1622float2(*reinterpret_cast<const __nv_bfloat162*>(Hin + r*256 + c));
                        float n0 = tanhf(fmaf(rr.x, h0, i0));
                        float n1 = tanhf(fmaf(rr.y, h1, i1));
                        __nv_bfloat162 o;
                        o.x = __float2bfloat16_rn(fmaf(zz.x, hh.x - n0, n0));   // (1-z)n + zH
                        o.y = __float2bfloat16_rn(fmaf(zz.y, hh.y - n1, n1));
                        *reinterpret_cast<__nv_bfloat162*>(C + r*256 + c) = o;
                    }
                }
            }
        }
    }
}

// ---------------------------------------------------------------------------
// Final head (tiny, fp32).  Hfin is perm-layout; invp maps target -> perm row.
// ---------------------------------------------------------------------------
__global__ void k_combined(const __nv_bfloat16* __restrict__ Hfin, const int* __restrict__ s,
                           const int* __restrict__ kk, const float* __restrict__ emb,
                           const float* __restrict__ combW, const float* __restrict__ combB,
                           const int* __restrict__ invp) {
    __shared__ float x[2*DV];
    int b = blockIdx.x, t = threadIdx.x;
    int srow = s[b], krow = kk[b];
    int pos = invp[b * NV + srow];
    x[t]      = __bfloat162float(Hfin[(size_t)pos*DV + t]);
    x[DV + t] = emb[(size_t)krow*DV + t];
    __syncthreads();
    const float* w = combW + (size_t)t * (2*DV);
    float acc = combB[t];
    #pragma unroll 8
    for (int j = 0; j < 2*DV; j++) acc = fmaf(x[j], w[j], acc);
    g_comb[b*DV + t] = geluf(acc);
}

__global__ void k_logits(const float* __restrict__ headW, const float* __restrict__ headB,
                         float* __restrict__ out) {
    __shared__ float cb[BV*DV];
    for (int i = threadIdx.x; i < BV*DV; i += 256) cb[i] = g_comb[i];
    __syncthreads();
    int warp = threadIdx.x >> 5, lane = threadIdx.x & 31;
    int n = blockIdx.x * 8 + warp;                     // 512 blocks x 8 warps = 4096
    const float4* w4 = reinterpret_cast<const float4*>(headW + (size_t)n*DV);
    float acc[BV];
    #pragma unroll
    for (int b = 0; b < BV; b++) acc[b] = 0.f;
    #pragma unroll
    for (int c = lane; c < DV/4; c += 32) {
        float4 wv = w4[c];
        #pragma unroll
        for (int b = 0; b < BV; b++) {
            const float* cbb = &cb[b*DV + c*4];
            acc[b] += wv.x*cbb[0] + wv.y*cbb[1] + wv.z*cbb[2] + wv.w*cbb[3];
        }
    }
    #pragma unroll
    for (int off = 16; off; off >>= 1)
        #pragma unroll
        for (int b = 0; b < BV; b++)
            acc[b] += __shfl_down_sync(0xFFFFFFFFu, acc[b], off);
    if (lane == 0) {
        float hb = headB[n];
        #pragma unroll
        for (int b = 0; b < BV; b++) out[b*NV + n] = acc[b] + hb;
    }
}

// ---------------------------------------------------------------------------
// Host launcher
// ---------------------------------------------------------------------------
extern "C" void kernel_launch(void* const* d_in, const int* in_sizes, int n_in,
                              void* d_out, int out_size) {
    const int*   p     = (const int*)d_in[0];
    const int*   s     = (const int*)d_in[1];
    const int*   kk    = (const int*)d_in[2];
    const float* emb   = (const float*)d_in[3];
    const float* W1    = (const float*)d_in[4];
    const float* b1    = (const float*)d_in[5];
    const float* W2    = (const float*)d_in[6];
    const float* b2    = (const float*)d_in[7];
    const float* Wih   = (const float*)d_in[8];
    const float* Whh   = (const float*)d_in[9];
    const float* bih   = (const float*)d_in[10];
    const float* bhh   = (const float*)d_in[11];
    const float* combW = (const float*)d_in[12];
    const float* combB = (const float*)d_in[13];
    const float* headW = (const float*)d_in[14];
    const float* headB = (const float*)d_in[15];
    float* out = (float*)d_out;

    void *pH0, *pH1, *pHid, *pMsgs, *pRz, *pEmbf, *pW1, *pW2, *pWih, *pWhh, *pBrz;
    void *pRowsP, *pA1, *pA10, *pInvp, *pCnt;
    cudaGetSymbolAddress(&pH0,  g_H0);
    cudaGetSymbolAddress(&pH1,  g_H1);
    cudaGetSymbolAddress(&pHid, g_hid);
    cudaGetSymbolAddress(&pMsgs,g_msgs);
    cudaGetSymbolAddress(&pRz,  g_rz);
    cudaGetSymbolAddress(&pEmbf,g_embf);
    cudaGetSymbolAddress(&pW1,  g_W1);
    cudaGetSymbolAddress(&pW2,  g_W2);
    cudaGetSymbolAddress(&pWih, g_Wih);
    cudaGetSymbolAddress(&pWhh, g_Whh);
    cudaGetSymbolAddress(&pBrz, g_brz);
    cudaGetSymbolAddress(&pRowsP,g_rowsP);
    cudaGetSymbolAddress(&pA1,  g_a1idx);
    cudaGetSymbolAddress(&pA10, g_a1idx0);
    cudaGetSymbolAddress(&pInvp,g_invp);
    cudaGetSymbolAddress(&pCnt, g_cnt);

    const int SM128 = 4*(128*40 + 128*40) * 2;     // 81920 B
    const int SM64  = 4*(64*40  + 128*40) * 2;     // 61440 B
    cudaFuncSetAttribute((const void*)k_gemm<0,128,false>, cudaFuncAttributeMaxDynamicSharedMemorySize, SM128);
    cudaFuncSetAttribute((const void*)k_gemm<0,128,true >, cudaFuncAttributeMaxDynamicSharedMemorySize, SM128);
    cudaFuncSetAttribute((const void*)k_gemm<1,128,false>, cudaFuncAttributeMaxDynamicSharedMemorySize, SM128);
    cudaFuncSetAttribute((const void*)k_gemm<2,128,true >, cudaFuncAttributeMaxDynamicSharedMemorySize, SM128);
    cudaFuncSetAttribute((const void*)k_gemm<3,64 ,true >, cudaFuncAttributeMaxDynamicSharedMemorySize, SM64);

    const __nv_bfloat16* bW1  = (const __nv_bfloat16*)pW1;
    const __nv_bfloat16* bW2  = (const __nv_bfloat16*)pW2;
    const __nv_bfloat16* bWih = (const __nv_bfloat16*)pWih;
    const __nv_bfloat16* bWhh = (const __nv_bfloat16*)pWhh;
    __nv_bfloat16* Hc   = (__nv_bfloat16*)pH0;
    __nv_bfloat16* Hn   = (__nv_bfloat16*)pH1;
    __nv_bfloat16* msgs = (__nv_bfloat16*)pMsgs;
    __nv_bfloat16* rz   = (__nv_bfloat16*)pRz;
    __nv_bfloat16* hid  = (__nv_bfloat16*)pHid;
    const int* cntP = (const int*)pCnt;

    // Launch order keeps a GEMM at launch #4 (ncu capture point):
    // prep(1), win_fill(2), compact(3), L0-hid(4).
    k_prep<<<1024, 256>>>(W1, W2, Wih, Whh, bih, bhh, emb);
    k_win_fill<<<MV/256, 256>>>(p);
    k_compact<<<MV/256, 256>>>();

    // Layer 0 MLP on NV shared emb rows (dense)
    k_gemm<0,128,false><<<PGRID, 256, SM128>>>(
        (__nv_bfloat16*)pEmbf, nullptr, bW1, nullptr, b1, nullptr, hid,
        nullptr, nullptr, nullptr, nullptr, 0, 256, 0, 1024, NV, 8);
    k_gemm<1,128,false><<<PGRID, 256, SM128>>>(
        hid, nullptr, bW2, nullptr, b2, nullptr, msgs,
        nullptr, nullptr, nullptr, nullptr, 0, 1024, 0, 256, NV, 2);

    // Hp init + rowsP composition (needs compact)
    k_h0p<<<(MV*32)/256, 256>>>(emb);

    for (int l = 0; l < LV; l++) {
        const int* a1 = (l == 0) ? (const int*)pA10 : (const int*)pA1;
        if (l > 0) {
            // MLP only on winner rows (compact): A = Hp gathered via rowsP.
            k_gemm<0,128,true><<<PGRID, 256, SM128>>>(
                Hc, nullptr, bW1, nullptr, b1, nullptr, hid,
                nullptr, nullptr, (const int*)pRowsP, cntP, 1, 256, 0, 1024, MV, 8);
            k_gemm<1,128,false><<<PGRID, 256, SM128>>>(
                hid, nullptr, bW2, nullptr, b2, nullptr, msgs,
                nullptr, nullptr, nullptr, cntP, 1, 1024, 0, 256, MV, 2);
        }
        // rz: sigmoid(msgs[a1]@Wih_rz^T + Hp@Whh_rz^T + brz), perm-dense.
        // Dynamic-K: loser tiles skip the gi half entirely (nk1=0).
        k_gemm<2,128,true><<<PGRID, 256, SM128>>>(
            msgs, Hc, bWih, bWhh, (float*)pBrz, nullptr, rz,
            nullptr, nullptr, a1, cntP, 3, 256, 256, 512, MV, 4);
        // n-gate + GRU update -> Hn (perm-dense), dynamic-K likewise.
        k_gemm<3,64,true><<<PGRID, 256, SM64>>>(
            msgs, Hc, bWih + 512*DV, bWhh + 512*DV, bih + 512, bhh + 512, Hn,
            rz, Hc, a1, cntP, 3, 256, 256, 256, MV, 2);
        __nv_bfloat16* t = Hc; Hc = Hn; Hn = t;
    }

    k_combined<<<BV, 256>>>(Hc, s, kk, emb, combW, combB, (const int*)pInvp);
    k_logits<<<NV/8, 256>>>(headW, headB, out);
}

// round 15
// speedup vs baseline: 1.0258x; 1.0258x over previous
#include <cuda_runtime.h>
#include <cuda_bf16.h>
#include <cstdint>

// Problem constants
#define BV 8
#define NV 4096
#define DV 256
#define HIDV 1024
#define LV 6
#define MV (BV*NV)          // 32768 rows

// ---------------------------------------------------------------------------
// Scratch (static __device__ — no allocation allowed)
// H lives in PERM layout: perm row i<cnt is the target whose winner slot is i
// (so the GRU's gi operand is msgs_compact[i] — identity, dense);
// loser targets occupy perm rows [cnt, MV).
// ---------------------------------------------------------------------------
__device__ __nv_bfloat16 g_H0[(size_t)MV*DV];          // 16 MB  (perm layout)
__device__ __nv_bfloat16 g_H1[(size_t)MV*DV];          // 16 MB  (perm layout)
__device__ __nv_bfloat16 g_hid[(size_t)MV*HIDV];       // 64 MB  (compact rows)
__device__ __nv_bfloat16 g_msgs[(size_t)(MV+8)*DV];    // 16 MB  (+ zero row at MV)
__device__ __nv_bfloat16 g_rz[(size_t)MV*512];         // 32 MB  (perm-dense)
__device__ __nv_bfloat16 g_embf[NV*DV];                // 2 MB   (bf16 emb, L0 MLP)
__device__ int   g_win[MV];     // target row -> winning in-batch source index or -1
__device__ int   g_rows[MV];    // slot -> global source row (natural)
__device__ int   g_rowsP[MV];   // slot -> source row in PERM space (hid A gather)
__device__ int   g_perm[MV];    // perm row -> target row
__device__ int   g_invp[MV];    // target row -> perm row
__device__ int   g_a1idx[MV];   // perm row -> msgs row (identity <cnt, else MV)
__device__ int   g_a1idx0[MV];  // L0 variant: perm row -> shared msgs row or MV
__device__ int   g_cnt;         // winner count
__device__ int   g_lcnt;        // loser count
__device__ __nv_bfloat16 g_W1[HIDV*DV];
__device__ __nv_bfloat16 g_W2[DV*HIDV];
__device__ __nv_bfloat16 g_Wih[3*DV*DV];
__device__ __nv_bfloat16 g_Whh[3*DV*DV];
__device__ float g_brz[2*DV];
__device__ float g_comb[BV*DV];

// ---------------------------------------------------------------------------
// Helpers
// ---------------------------------------------------------------------------
__device__ __forceinline__ float geluf(float x) {
    return 0.5f * x * (1.0f + erff(x * 0.7071067811865476f));
}
__device__ __forceinline__ float sigmf(float x) {
    return 1.0f / (1.0f + __expf(-x));
}
__device__ __forceinline__ void cpasync16(uint32_t dst, const void* src) {
    asm volatile("cp.async.cg.shared.global [%0], [%1], 16;\n" :: "r"(dst), "l"(src));
}
__device__ __forceinline__ void ldsm_x4(unsigned r[4], uint32_t addr) {
    asm volatile("ldmatrix.sync.aligned.m8n8.x4.shared.b16 {%0,%1,%2,%3}, [%4];\n"
                 : "=r"(r[0]), "=r"(r[1]), "=r"(r[2]), "=r"(r[3]) : "r"(addr));
}
__device__ __forceinline__ void mma_bf16(float c[4], const unsigned a[4], const unsigned b[2]) {
    asm volatile(
        "mma.sync.aligned.m16n8k16.row.col.f32.bf16.bf16.f32 "
        "{%0,%1,%2,%3}, {%4,%5,%6,%7}, {%8,%9}, {%0,%1,%2,%3};\n"
        : "+f"(c[0]), "+f"(c[1]), "+f"(c[2]), "+f"(c[3])
        : "r"(a[0]), "r"(a[1]), "r"(a[2]), "r"(a[3]), "r"(b[0]), "r"(b[1]));
}

// ---------------------------------------------------------------------------
// Prep kernels
// ---------------------------------------------------------------------------
__global__ void k_prep(const float* __restrict__ W1, const float* __restrict__ W2,
                       const float* __restrict__ Wih, const float* __restrict__ Whh,
                       const float* __restrict__ bih, const float* __restrict__ bhh) {
    int i = blockIdx.x * 256 + threadIdx.x;           // grid covers HIDV*DV = 262144
    if (i < HIDV*DV) { g_W1[i] = __float2bfloat16_rn(W1[i]); g_W2[i] = __float2bfloat16_rn(W2[i]); }
    if (i < 3*DV*DV) { g_Wih[i] = __float2bfloat16_rn(Wih[i]); g_Whh[i] = __float2bfloat16_rn(Whh[i]); }
    if (i < 2*DV)    { g_brz[i] = bih[i] + bhh[i]; }
}

// bf16 copy of emb (L0 MLP operand), vectorized 8 elems/thread.
__global__ void k_embf(const float* __restrict__ emb) {
    size_t base = ((size_t)blockIdx.x * 256 + threadIdx.x) * 8;   // NV*DV/8 threads
    float4 a = *reinterpret_cast<const float4*>(emb + base);
    float4 b = *reinterpret_cast<const float4*>(emb + base + 4);
    __nv_bfloat162 o[4];
    o[0].x = __float2bfloat16_rn(a.x); o[0].y = __float2bfloat16_rn(a.y);
    o[1].x = __float2bfloat16_rn(a.z); o[1].y = __float2bfloat16_rn(a.w);
    o[2].x = __float2bfloat16_rn(b.x); o[2].y = __float2bfloat16_rn(b.y);
    o[3].x = __float2bfloat16_rn(b.z); o[3].y = __float2bfloat16_rn(b.w);
    *reinterpret_cast<uint4*>(g_embf + base) = *reinterpret_cast<uint4*>(o);
}

__global__ void k_win_init() {
    int i = blockIdx.x * 256 + threadIdx.x;           // MV
    g_win[i] = -1;
    g_rows[i] = 0;
    g_rowsP[i] = 0;
    g_perm[i] = 0;
    g_invp[i] = 0;
    g_a1idx[i]  = MV;                                 // default: zero msgs row
    g_a1idx0[i] = MV;
    if (i < DV) g_msgs[(size_t)MV*DV + i] = __float2bfloat16_rn(0.f);
    if (i == 0) { g_cnt = 0; g_lcnt = 0; }
}
__global__ void k_win_fill(const int* __restrict__ p) {
    int i = blockIdx.x * 256 + threadIdx.x;           // MV
    int b = i >> 12, t = i & 4095;
    atomicMax(&g_win[(b << 12) + p[i]], t);
}
// Permutation build. Slot order is replay-dependent but output-invariant:
// every consumer indexes through the tables and rows are independent.
__global__ void k_compact() {
    int t = blockIdx.x * 256 + threadIdx.x;           // MV target rows
    int w = g_win[t];
    if (w >= 0) {
        int slot = atomicAdd(&g_cnt, 1);
        int src = ((t >> 12) << 12) | w;
        g_rows[slot]   = src;
        g_perm[slot]   = t;
        g_invp[t]      = slot;
        g_a1idx[slot]  = slot;      // identity: msgs compact
        g_a1idx0[slot] = w;         // L0: msgs shared across batch
    } else {
        int l = atomicAdd(&g_lcnt, 1);
        g_perm[MV - 1 - l] = t;
        g_invp[t] = MV - 1 - l;
    }
}
// Compose: perm-space source rows for the hid GEMM's A gather.
__global__ void k_compact2() {
    int slot = blockIdx.x * 256 + threadIdx.x;
    if (slot < g_cnt) g_rowsP[slot] = g_invp[g_rows[slot]];
}
// Initialize Hp (perm layout) from emb: Hp[i] = bf16(emb[perm[i] mod NV]).
__global__ void k_h0p(const float* __restrict__ emb) {
    int idx = blockIdx.x * 256 + threadIdx.x;         // MV*32 chunks of 8 elems
    int i  = idx >> 5;
    int c8 = idx & 31;
    int er = g_perm[i] & (NV - 1);
    const float* s = emb + (size_t)er * DV + c8 * 8;
    float4 a = *reinterpret_cast<const float4*>(s);
    float4 b = *reinterpret_cast<const float4*>(s + 4);
    __nv_bfloat162 o[4];
    o[0].x = __float2bfloat16_rn(a.x); o[0].y = __float2bfloat16_rn(a.y);
    o[1].x = __float2bfloat16_rn(a.z); o[1].y = __float2bfloat16_rn(a.w);
    o[2].x = __float2bfloat16_rn(b.x); o[2].y = __float2bfloat16_rn(b.y);
    o[3].x = __float2bfloat16_rn(b.z); o[3].y = __float2bfloat16_rn(b.w);
    *reinterpret_cast<uint4*>(g_H0 + (size_t)i * DV + c8 * 8) = *reinterpret_cast<uint4*>(o);
}

// ---------------------------------------------------------------------------
// BF16 GEMM, BMx128 tile, KC=32, 4-stage cp.async pipeline, TWO k-tiles per
// __syncthreads (halved barrier count), fused epilogues:
//   MODE 0: C = bf16(gelu(A1@Wa^T + biasA))                (hid)
//   MODE 1: C = bf16(A1@Wa^T + biasA)                      (msgs)
//   MODE 2: C = bf16(sigmoid(A1@Wa^T + A2@Wb^T + biasA))   (rz; all perm-dense)
//   MODE 3: GRU n-gate + state update, dual accumulators   (Hn; all perm-dense)
// GATHER: A1 rows indirected through tblA1 (rowsP / a1idx).
// exitMode: 0 none; 1 winner region (exit if rowB >= cnt);
//           3 dynamic-K (blocks with rowB >= cnt skip the A1 K-range).
// All NK values (8/16/32) are even; nk1 in {0,8} so the MODE-3 accumulator
// switch never straddles a tile pair.
// Smem rows padded to 40 bf16 (80 B stride) => conflict-free ldmatrix.
// ---------------------------------------------------------------------------
template<int BM, bool GATHER>
__device__ __forceinline__ void load_tile(const __nv_bfloat16* __restrict__ Asrc,
                                          const int* __restrict__ tblA,
                                          const __nv_bfloat16* __restrict__ Wsrc,
                                          int lda, int kcol, long rowB, int colB,
                                          uint32_t smBase, int asOff, int bsOff, int tid) {
    #pragma unroll
    for (int i = 0; i < (BM*4)/256; i++) {
        int idx = i*256 + tid; int r = idx >> 2, ck = idx & 3;
        long ar = GATHER ? (long)tblA[rowB + r] : (rowB + r);
        cpasync16(smBase + (unsigned)((asOff + r*40 + ck*8) * 2),
                  Asrc + ar * (long)lda + kcol + ck*8);
    }
    #pragma unroll
    for (int i = 0; i < 2; i++) {
        int idx = i*256 + tid; int r = idx >> 2, ck = idx & 3;
        cpasync16(smBase + (unsigned)((bsOff + r*40 + ck*8) * 2),
                  Wsrc + (long)(colB + r) * lda + kcol + ck*8);
    }
    asm volatile("cp.async.commit_group;\n" ::);
}

template<int MT>
__device__ __forceinline__ void compute_tile(uint32_t aB, uint32_t bB, int lane,
                                             int wr0, int wc0, float acc[][4][4]) {
    #pragma unroll
    for (int kst = 0; kst < 2; kst++) {
        unsigned a[MT][4], b[4][2];
        int arow = wr0 + (lane & 15);
        int acol = kst*16 + (lane >> 4) * 8;
        #pragma unroll
        for (int i = 0; i < MT; i++)
            ldsm_x4(a[i], aB + (unsigned)(((arow + i*16) * 40 + acol) * 2));
        #pragma unroll
        for (int jj = 0; jj < 2; jj++) {
            unsigned t[4];
            int brow = wc0 + jj*16 + (lane & 7) + ((lane >> 4) & 1) * 8;
            int bcol = kst*16 + ((lane >> 3) & 1) * 8;
            ldsm_x4(t, bB + (unsigned)((brow * 40 + bcol) * 2));
            b[jj*2][0]   = t[0]; b[jj*2][1]   = t[1];
            b[jj*2+1][0] = t[2]; b[jj*2+1][1] = t[3];
        }
        #pragma unroll
        for (int i = 0; i < MT; i++)
            #pragma unroll
            for (int j = 0; j < 4; j++)
                mma_bf16(acc[i][j], a[i], b[j]);
    }
}

template<int MODE, int BM, bool GATHER>
__global__ void __launch_bounds__(256)
k_gemm(const __nv_bfloat16* __restrict__ A1, const __nv_bfloat16* __restrict__ A2,
       const __nv_bfloat16* __restrict__ Wa, const __nv_bfloat16* __restrict__ Wb,
       const float* __restrict__ biasA, const float* __restrict__ biasB,
       __nv_bfloat16* __restrict__ C,
       const __nv_bfloat16* __restrict__ rzb, const __nv_bfloat16* __restrict__ Hin,
       const int* __restrict__ tblA1, const int* __restrict__ cntPtr, int exitMode,
       int K1, int K2, int Nout) {
    constexpr int MT = BM / 32;       // warp m-tiles of 16
    extern __shared__ __nv_bfloat16 sm[];
    const int tid = threadIdx.x, lane = tid & 31, warp = tid >> 5;
    const int wr0 = (warp >> 2) * (BM/2), wc0 = (warp & 3) * 32;
    const long rowB = (long)blockIdx.x * BM;
    const int  colB = blockIdx.y * 128;

    int nk1 = K1 / 32;
    if (exitMode == 1) {
        if (rowB >= *cntPtr) return;                       // compact region only
    } else if (exitMode == 3) {
        if (rowB >= *cntPtr) nk1 = 0;                      // losers: skip gi half
    }

    uint32_t smBase = (uint32_t)__cvta_generic_to_shared(sm);
    const int asz = BM * 40, bsz = 128 * 40;      // elements per stage

    float acc[MT][4][4];
    float acc2[MT][4][4];
    #pragma unroll
    for (int i = 0; i < MT; i++)
        #pragma unroll
        for (int j = 0; j < 4; j++)
            #pragma unroll
            for (int e = 0; e < 4; e++) {
                acc[i][j][e] = 0.f;
                if (MODE == 3) acc2[i][j][e] = 0.f;
            }

    const int NK = nk1 + K2 / 32;     // always even (8/16/32)

    auto issue = [&](int k, int stage) {
        if (k < nk1)
            load_tile<BM, GATHER>(A1, tblA1, Wa, K1, k*32, rowB, colB, smBase,
                                  stage*asz, 4*asz + stage*bsz, tid);
        else
            load_tile<BM, false >(A2, nullptr, Wb, K2, (k - nk1)*32, rowB, colB, smBase,
                                  stage*asz, 4*asz + stage*bsz, tid);
    };

    // Prologue: groups 0,1 in stages 0,1.
    issue(0, 0); issue(1, 1);

    for (int kt = 0; kt < NK; kt += 2) {
        // All committed groups are exactly 0..kt+1 — wait for them all.
        asm volatile("cp.async.wait_group 0;\n" ::);
        __syncthreads();                  // releases stages (kt-2)&3, (kt-1)&3
        if (kt + 2 < NK) issue(kt + 2, (kt + 2) & 3);
        if (kt + 3 < NK) issue(kt + 3, (kt + 3) & 3);
        const int st0 = kt & 3, st1 = (kt + 1) & 3;
        uint32_t aB0 = smBase + (unsigned)((st0 * asz) * 2);
        uint32_t bB0 = smBase + (unsigned)((4*asz + st0 * bsz) * 2);
        uint32_t aB1 = smBase + (unsigned)((st1 * asz) * 2);
        uint32_t bB1 = smBase + (unsigned)((4*asz + st1 * bsz) * 2);
        if (MODE == 3 && kt >= nk1) {
            compute_tile<MT>(aB0, bB0, lane, wr0, wc0, acc2);
            compute_tile<MT>(aB1, bB1, lane, wr0, wc0, acc2);
        } else {
            compute_tile<MT>(aB0, bB0, lane, wr0, wc0, acc);
            compute_tile<MT>(aB1, bB1, lane, wr0, wc0, acc);
        }
    }

    const int laneR = lane >> 2, laneC = (lane & 3) * 2;
    #pragma unroll
    for (int i = 0; i < MT; i++) {
        #pragma unroll
        for (int e = 0; e < 2; e++) {
            long r = rowB + wr0 + i*16 + laneR + e*8;
            #pragma unroll
            for (int j = 0; j < 4; j++) {
                int c = colB + wc0 + j*8 + laneC;
                float v0 = acc[i][j][e*2], v1 = acc[i][j][e*2+1];
                if (MODE == 0) {
                    __nv_bfloat162 o;
                    o.x = __float2bfloat16_rn(geluf(v0 + biasA[c]));
                    o.y = __float2bfloat16_rn(geluf(v1 + biasA[c+1]));
                    *reinterpret_cast<__nv_bfloat162*>(C + r*Nout + c) = o;
                } else if (MODE == 1) {
                    __nv_bfloat162 o;
                    o.x = __float2bfloat16_rn(v0 + biasA[c]);
                    o.y = __float2bfloat16_rn(v1 + biasA[c+1]);
                    *reinterpret_cast<__nv_bfloat162*>(C + r*Nout + c) = o;
                } else if (MODE == 2) {
                    __nv_bfloat162 o;
                    o.x = __float2bfloat16_rn(sigmf(v0 + biasA[c]));
                    o.y = __float2bfloat16_rn(sigmf(v1 + biasA[c+1]));
                    *reinterpret_cast<__nv_bfloat162*>(C + r*Nout + c) = o;
                } else {
                    // i-gate half = acc (zero for loser blocks, nk1=0)
                    float i0 = v0 + biasA[c],            i1 = v1 + biasA[c+1];
                    float h0 = acc2[i][j][e*2] + biasB[c];
                    float h1 = acc2[i][j][e*2+1] + biasB[c+1];
                    float2 rr = __bfloat1622float2(*reinterpret_cast<const __nv_bfloat162*>(rzb + r*512 + c));
                    float2 zz = __bfloat1622float2(*reinterpret_cast<const __nv_bfloat162*>(rzb + r*512 + 256 + c));
                    float2 hh = __bfloat1622float2(*reinterpret_cast<const __nv_bfloat162*>(Hin + r*256 + c));
                    float n0 = tanhf(fmaf(rr.x, h0, i0));
                    float n1 = tanhf(fmaf(rr.y, h1, i1));
                    __nv_bfloat162 o;
                    o.x = __float2bfloat16_rn(fmaf(zz.x, hh.x - n0, n0));   // (1-z)n + zH
                    o.y = __float2bfloat16_rn(fmaf(zz.y, hh.y - n1, n1));
                    *reinterpret_cast<__nv_bfloat162*>(C + r*256 + c) = o;
                }
            }
        }
    }
}

// ---------------------------------------------------------------------------
// Final head (tiny, fp32).  Hfin is perm-layout; invp maps target -> perm row.
// ---------------------------------------------------------------------------
__global__ void k_combined(const __nv_bfloat16* __restrict__ Hfin, const int* __restrict__ s,
                           const int* __restrict__ kk, const float* __restrict__ emb,
                           const float* __restrict__ combW, const float* __restrict__ combB,
                           const int* __restrict__ invp) {
    __shared__ float x[2*DV];
    int b = blockIdx.x, t = threadIdx.x;
    int srow = s[b], krow = kk[b];
    int pos = invp[b * NV + srow];
    x[t]      = __bfloat162float(Hfin[(size_t)pos*DV + t]);
    x[DV + t] = emb[(size_t)krow*DV + t];
    __syncthreads();
    const float* w = combW + (size_t)t * (2*DV);
    float acc = combB[t];
    #pragma unroll 8
    for (int j = 0; j < 2*DV; j++) acc = fmaf(x[j], w[j], acc);
    g_comb[b*DV + t] = geluf(acc);
}

__global__ void k_logits(const float* __restrict__ headW, const float* __restrict__ headB,
                         float* __restrict__ out) {
    __shared__ float cb[BV*DV];
    for (int i = threadIdx.x; i < BV*DV; i += 256) cb[i] = g_comb[i];
    __syncthreads();
    int warp = threadIdx.x >> 5, lane = threadIdx.x & 31;
    int n = blockIdx.x * 8 + warp;                     // 512 blocks x 8 warps = 4096
    const float4* w4 = reinterpret_cast<const float4*>(headW + (size_t)n*DV);
    float acc[BV];
    #pragma unroll
    for (int b = 0; b < BV; b++) acc[b] = 0.f;
    #pragma unroll
    for (int c = lane; c < DV/4; c += 32) {
        float4 wv = w4[c];
        #pragma unroll
        for (int b = 0; b < BV; b++) {
            const float* cbb = &cb[b*DV + c*4];
            acc[b] += wv.x*cbb[0] + wv.y*cbb[1] + wv.z*cbb[2] + wv.w*cbb[3];
        }
    }
    #pragma unroll
    for (int off = 16; off; off >>= 1)
        #pragma unroll
        for (int b = 0; b < BV; b++)
            acc[b] += __shfl_down_sync(0xFFFFFFFFu, acc[b], off);
    if (lane == 0) {
        float hb = headB[n];
        #pragma unroll
        for (int b = 0; b < BV; b++) out[b*NV + n] = acc[b] + hb;
    }
}

// ---------------------------------------------------------------------------
// Host launcher
// ---------------------------------------------------------------------------
extern "C" void kernel_launch(void* const* d_in, const int* in_sizes, int n_in,
                              void* d_out, int out_size) {
    const int*   p     = (const int*)d_in[0];
    const int*   s     = (const int*)d_in[1];
    const int*   kk    = (const int*)d_in[2];
    const float* emb   = (const float*)d_in[3];
    const float* W1    = (const float*)d_in[4];
    const float* b1    = (const float*)d_in[5];
    const float* W2    = (const float*)d_in[6];
    const float* b2    = (const float*)d_in[7];
    const float* Wih   = (const float*)d_in[8];
    const float* Whh   = (const float*)d_in[9];
    const float* bih   = (const float*)d_in[10];
    const float* bhh   = (const float*)d_in[11];
    const float* combW = (const float*)d_in[12];
    const float* combB = (const float*)d_in[13];
    const float* headW = (const float*)d_in[14];
    const float* headB = (const float*)d_in[15];
    float* out = (float*)d_out;

    void *pH0, *pH1, *pHid, *pMsgs, *pRz, *pEmbf, *pW1, *pW2, *pWih, *pWhh, *pBrz;
    void *pRowsP, *pA1, *pA10, *pInvp, *pCnt;
    cudaGetSymbolAddress(&pH0,  g_H0);
    cudaGetSymbolAddress(&pH1,  g_H1);
    cudaGetSymbolAddress(&pHid, g_hid);
    cudaGetSymbolAddress(&pMsgs,g_msgs);
    cudaGetSymbolAddress(&pRz,  g_rz);
    cudaGetSymbolAddress(&pEmbf,g_embf);
    cudaGetSymbolAddress(&pW1,  g_W1);
    cudaGetSymbolAddress(&pW2,  g_W2);
    cudaGetSymbolAddress(&pWih, g_Wih);
    cudaGetSymbolAddress(&pWhh, g_Whh);
    cudaGetSymbolAddress(&pBrz, g_brz);
    cudaGetSymbolAddress(&pRowsP,g_rowsP);
    cudaGetSymbolAddress(&pA1,  g_a1idx);
    cudaGetSymbolAddress(&pA10, g_a1idx0);
    cudaGetSymbolAddress(&pInvp,g_invp);
    cudaGetSymbolAddress(&pCnt, g_cnt);

    const int SM128 = 4*(128*40 + 128*40) * 2;     // 81920 B
    const int SM64  = 4*(64*40  + 128*40) * 2;     // 61440 B
    cudaFuncSetAttribute((const void*)k_gemm<0,128,false>, cudaFuncAttributeMaxDynamicSharedMemorySize, SM128);
    cudaFuncSetAttribute((const void*)k_gemm<0,128,true >, cudaFuncAttributeMaxDynamicSharedMemorySize, SM128);
    cudaFuncSetAttribute((const void*)k_gemm<1,128,false>, cudaFuncAttributeMaxDynamicSharedMemorySize, SM128);
    cudaFuncSetAttribute((const void*)k_gemm<1,64 ,false>, cudaFuncAttributeMaxDynamicSharedMemorySize, SM64);
    cudaFuncSetAttribute((const void*)k_gemm<2,128,true >, cudaFuncAttributeMaxDynamicSharedMemorySize, SM128);
    cudaFuncSetAttribute((const void*)k_gemm<3,64 ,true >, cudaFuncAttributeMaxDynamicSharedMemorySize, SM64);

    const __nv_bfloat16* bW1  = (const __nv_bfloat16*)pW1;
    const __nv_bfloat16* bW2  = (const __nv_bfloat16*)pW2;
    const __nv_bfloat16* bWih = (const __nv_bfloat16*)pWih;
    const __nv_bfloat16* bWhh = (const __nv_bfloat16*)pWhh;
    __nv_bfloat16* Hc   = (__nv_bfloat16*)pH0;
    __nv_bfloat16* Hn   = (__nv_bfloat16*)pH1;
    __nv_bfloat16* msgs = (__nv_bfloat16*)pMsgs;
    __nv_bfloat16* rz   = (__nv_bfloat16*)pRz;
    __nv_bfloat16* hid  = (__nv_bfloat16*)pHid;
    const int* cntP = (const int*)pCnt;

    // Order keeps a GEMM at launch #4 (ncu capture point): prep(1), embf(2),
    // win_init(3), L0-hid(4). L0 MLP depends only on prep+embf.
    k_prep<<<1024, 256>>>(W1, W2, Wih, Whh, bih, bhh);
    k_embf<<<(NV*DV/8)/256, 256>>>(emb);
    k_win_init<<<MV/256, 256>>>();

    // Layer 0 MLP on NV shared emb rows (dense)
    k_gemm<0,128,false><<<dim3(NV/128, 8), 256, SM128>>>(
        (__nv_bfloat16*)pEmbf, nullptr, bW1, nullptr, b1, nullptr, hid,
        nullptr, nullptr, nullptr, nullptr, 0, 256, 0, 1024);
    k_gemm<1,128,false><<<dim3(NV/128, 2), 256, SM128>>>(
        hid, nullptr, bW2, nullptr, b2, nullptr, msgs,
        nullptr, nullptr, nullptr, nullptr, 0, 1024, 0, 256);

    // Permutation tables + Hp init
    k_win_fill<<<MV/256, 256>>>(p);
    k_compact<<<MV/256, 256>>>();
    k_compact2<<<MV/256, 256>>>();
    k_h0p<<<(MV*32)/256, 256>>>(emb);

    for (int l = 0; l < LV; l++) {
        const int* a1 = (l == 0) ? (const int*)pA10 : (const int*)pA1;
        if (l > 0) {
            // MLP only on winner rows (compact): A = Hp gathered via rowsP.
            k_gemm<0,128,true><<<dim3(MV/128, 8), 256, SM128>>>(
                Hc, nullptr, bW1, nullptr, b1, nullptr, hid,
                nullptr, nullptr, (const int*)pRowsP, cntP, 1, 256, 0, 1024);
            // msgs: BM=64 to fix wave quantization (324 -> ~648 active blocks).
            k_gemm<1,64,false><<<dim3(MV/64, 2), 256, SM64>>>(
                hid, nullptr, bW2, nullptr, b2, nullptr, msgs,
                nullptr, nullptr, nullptr, cntP, 1, 1024, 0, 256);
        }
        // rz: sigmoid(msgs[a1]@Wih_rz^T + Hp@Whh_rz^T + brz), perm-dense.
        // Dynamic-K: loser blocks skip the gi half entirely (nk1=0).
        k_gemm<2,128,true><<<dim3(MV/128, 4), 256, SM128>>>(
            msgs, Hc, bWih, bWhh, (float*)pBrz, nullptr, rz,
            nullptr, nullptr, a1, cntP, 3, 256, 256, 512);
        // n-gate + GRU update -> Hn (perm-dense), dynamic-K likewise.
        k_gemm<3,64,true><<<dim3(MV/64, 2), 256, SM64>>>(
            msgs, Hc, bWih + 512*DV, bWhh + 512*DV, bih + 512, bhh + 512, Hn,
            rz, Hc, a1, cntP, 3, 256, 256, 256);
        __nv_bfloat16* t = Hc; Hc = Hn; Hn = t;
    }

    k_combined<<<BV, 256>>>(Hc, s, kk, emb, combW, combB, (const int*)pInvp);
    k_logits<<<NV/8, 256>>>(headW, headB, out);
}

// round 16
// speedup vs baseline: 1.0334x; 1.0074x over previous
#include <cuda_runtime.h>
#include <cuda_bf16.h>
#include <cstdint>

// Problem constants
#define BV 8
#define NV 4096
#define DV 256
#define HIDV 1024
#define LV 6
#define MV (BV*NV)          // 32768 rows

// ---------------------------------------------------------------------------
// Scratch (static __device__ — no allocation allowed)
// H lives in PERM layout: perm row i<cnt is the target whose winner slot is i
// (so the GRU's gi operand is msgs_compact[i] — identity, dense);
// loser targets occupy perm rows [cnt, MV).
// ---------------------------------------------------------------------------
__device__ __nv_bfloat16 g_H0[(size_t)MV*DV];          // 16 MB  (perm layout)
__device__ __nv_bfloat16 g_H1[(size_t)MV*DV];          // 16 MB  (perm layout)
__device__ __nv_bfloat16 g_hid[(size_t)MV*HIDV];       // 64 MB  (compact rows)
__device__ __nv_bfloat16 g_msgs[(size_t)(MV+8)*DV];    // 16 MB  (+ zero row at MV)
__device__ __nv_bfloat16 g_rz[(size_t)MV*512];         // 32 MB  (perm-dense)
__device__ __nv_bfloat16 g_embf[NV*DV];                // 2 MB   (bf16 emb, L0 MLP)
__device__ int   g_win[MV];     // target row -> winning in-batch source index or -1
__device__ int   g_rows[MV];    // slot -> global source row (natural)
__device__ int   g_rowsP[MV];   // slot -> source row in PERM space (hid A gather)
__device__ int   g_perm[MV];    // perm row -> target row
__device__ int   g_invp[MV];    // target row -> perm row
__device__ int   g_a1idx[MV];   // perm row -> msgs row (identity <cnt, else MV)
__device__ int   g_a1idx0[MV];  // L0 variant: perm row -> shared msgs row or MV
__device__ int   g_cnt;         // winner count
__device__ int   g_lcnt;        // loser count
__device__ __nv_bfloat16 g_W1[HIDV*DV];
__device__ __nv_bfloat16 g_W2[DV*HIDV];
__device__ __nv_bfloat16 g_Wih[3*DV*DV];
__device__ __nv_bfloat16 g_Whh[3*DV*DV];
__device__ float g_brz[2*DV];
__device__ float g_comb[BV*DV];

// ---------------------------------------------------------------------------
// Helpers
// ---------------------------------------------------------------------------
__device__ __forceinline__ float geluf(float x) {
    return 0.5f * x * (1.0f + erff(x * 0.7071067811865476f));
}
__device__ __forceinline__ float sigmf(float x) {
    return 1.0f / (1.0f + __expf(-x));
}
__device__ __forceinline__ void cpasync16(uint32_t dst, const void* src) {
    asm volatile("cp.async.cg.shared.global [%0], [%1], 16;\n" :: "r"(dst), "l"(src));
}
__device__ __forceinline__ void ldsm_x4(unsigned r[4], uint32_t addr) {
    asm volatile("ldmatrix.sync.aligned.m8n8.x4.shared.b16 {%0,%1,%2,%3}, [%4];\n"
                 : "=r"(r[0]), "=r"(r[1]), "=r"(r[2]), "=r"(r[3]) : "r"(addr));
}
__device__ __forceinline__ void mma_bf16(float c[4], const unsigned a[4], const unsigned b[2]) {
    asm volatile(
        "mma.sync.aligned.m16n8k16.row.col.f32.bf16.bf16.f32 "
        "{%0,%1,%2,%3}, {%4,%5,%6,%7}, {%8,%9}, {%0,%1,%2,%3};\n"
        : "+f"(c[0]), "+f"(c[1]), "+f"(c[2]), "+f"(c[3])
        : "r"(a[0]), "r"(a[1]), "r"(a[2]), "r"(a[3]), "r"(b[0]), "r"(b[1]));
}

// ---------------------------------------------------------------------------
// Prep (merged: weight rounding + bf16 emb copy + winner-table init)
// ---------------------------------------------------------------------------
__global__ void k_prep(const float* __restrict__ W1, const float* __restrict__ W2,
                       const float* __restrict__ Wih, const float* __restrict__ Whh,
                       const float* __restrict__ bih, const float* __restrict__ bhh,
                       const float* __restrict__ emb) {
    int i = blockIdx.x * 256 + threadIdx.x;           // grid covers HIDV*DV = 262144
    if (i < HIDV*DV) { g_W1[i] = __float2bfloat16_rn(W1[i]); g_W2[i] = __float2bfloat16_rn(W2[i]); }
    if (i < 3*DV*DV) { g_Wih[i] = __float2bfloat16_rn(Wih[i]); g_Whh[i] = __float2bfloat16_rn(Whh[i]); }
    if (i < 2*DV)    { g_brz[i] = bih[i] + bhh[i]; }
    if (i < NV*DV/8) {
        size_t base = (size_t)i * 8;
        float4 a = *reinterpret_cast<const float4*>(emb + base);
        float4 b = *reinterpret_cast<const float4*>(emb + base + 4);
        __nv_bfloat162 o[4];
        o[0].x = __float2bfloat16_rn(a.x); o[0].y = __float2bfloat16_rn(a.y);
        o[1].x = __float2bfloat16_rn(a.z); o[1].y = __float2bfloat16_rn(a.w);
        o[2].x = __float2bfloat16_rn(b.x); o[2].y = __float2bfloat16_rn(b.y);
        o[3].x = __float2bfloat16_rn(b.z); o[3].y = __float2bfloat16_rn(b.w);
        *reinterpret_cast<uint4*>(g_embf + base) = *reinterpret_cast<uint4*>(o);
    }
    if (i < MV) {
        g_win[i] = -1;
        g_rows[i] = 0;
        g_rowsP[i] = 0;
        g_perm[i] = 0;
        g_invp[i] = 0;
        g_a1idx[i]  = MV;                             // default: zero msgs row
        g_a1idx0[i] = MV;
    }
    if (i < DV) g_msgs[(size_t)MV*DV + i] = __float2bfloat16_rn(0.f);
    if (i == 0) { g_cnt = 0; g_lcnt = 0; }
}

__global__ void k_win_fill(const int* __restrict__ p) {
    int i = blockIdx.x * 256 + threadIdx.x;           // MV
    int b = i >> 12, t = i & 4095;
    atomicMax(&g_win[(b << 12) + p[i]], t);
}
// Permutation build. Slot order is replay-dependent but output-invariant:
// every consumer indexes through the tables and rows are independent.
__global__ void k_compact() {
    int t = blockIdx.x * 256 + threadIdx.x;           // MV target rows
    int w = g_win[t];
    if (w >= 0) {
        int slot = atomicAdd(&g_cnt, 1);
        int src = ((t >> 12) << 12) | w;
        g_rows[slot]   = src;
        g_perm[slot]   = t;
        g_invp[t]      = slot;
        g_a1idx[slot]  = slot;      // identity: msgs compact
        g_a1idx0[slot] = w;         // L0: msgs shared across batch
    } else {
        int l = atomicAdd(&g_lcnt, 1);
        g_perm[MV - 1 - l] = t;
        g_invp[t] = MV - 1 - l;
    }
}
// Hp init (perm layout) from emb + rowsP composition (merged compact2).
__global__ void k_h0p(const float* __restrict__ emb) {
    int idx = blockIdx.x * 256 + threadIdx.x;         // MV*32 chunks of 8 elems
    if (idx < MV && idx < g_cnt) g_rowsP[idx] = g_invp[g_rows[idx]];
    int i  = idx >> 5;
    int c8 = idx & 31;
    int er = g_perm[i] & (NV - 1);
    const float* s = emb + (size_t)er * DV + c8 * 8;
    float4 a = *reinterpret_cast<const float4*>(s);
    float4 b = *reinterpret_cast<const float4*>(s + 4);
    __nv_bfloat162 o[4];
    o[0].x = __float2bfloat16_rn(a.x); o[0].y = __float2bfloat16_rn(a.y);
    o[1].x = __float2bfloat16_rn(a.z); o[1].y = __float2bfloat16_rn(a.w);
    o[2].x = __float2bfloat16_rn(b.x); o[2].y = __float2bfloat16_rn(b.y);
    o[3].x = __float2bfloat16_rn(b.z); o[3].y = __float2bfloat16_rn(b.w);
    *reinterpret_cast<uint4*>(g_H0 + (size_t)i * DV + c8 * 8) = *reinterpret_cast<uint4*>(o);
}

// ---------------------------------------------------------------------------
// BF16 GEMM, BMx128 tile, KC=32, 4-stage cp.async pipeline, TWO k-tiles per
// __syncthreads (halved barrier count), fused epilogues:
//   MODE 0: C = bf16(gelu(A1@Wa^T + biasA))                (hid)
//   MODE 1: C = bf16(A1@Wa^T + biasA)                      (msgs)
//   MODE 2: C = bf16(sigmoid(A1@Wa^T + A2@Wb^T + biasA))   (rz; all perm-dense)
//   MODE 3: GRU n-gate + state update, dual accumulators   (Hn; all perm-dense)
// GATHER: A1 rows indirected through tblA1 (rowsP / a1idx).
// exitMode: 0 none; 1 winner region (exit if rowB >= cnt);
//           3 dynamic-K (blocks with rowB >= cnt skip the A1 K-range).
// All NK values (8/16/32) are even; nk1 in {0,8} so the MODE-3 accumulator
// switch never straddles a tile pair.
// Smem rows padded to 40 bf16 (80 B stride) => conflict-free ldmatrix.
// ---------------------------------------------------------------------------
template<int BM, bool GATHER>
__device__ __forceinline__ void load_tile(const __nv_bfloat16* __restrict__ Asrc,
                                          const int* __restrict__ tblA,
                                          const __nv_bfloat16* __restrict__ Wsrc,
                                          int lda, int kcol, long rowB, int colB,
                                          uint32_t smBase, int asOff, int bsOff, int tid) {
    #pragma unroll
    for (int i = 0; i < (BM*4)/256; i++) {
        int idx = i*256 + tid; int r = idx >> 2, ck = idx & 3;
        long ar = GATHER ? (long)tblA[rowB + r] : (rowB + r);
        cpasync16(smBase + (unsigned)((asOff + r*40 + ck*8) * 2),
                  Asrc + ar * (long)lda + kcol + ck*8);
    }
    #pragma unroll
    for (int i = 0; i < 2; i++) {
        int idx = i*256 + tid; int r = idx >> 2, ck = idx & 3;
        cpasync16(smBase + (unsigned)((bsOff + r*40 + ck*8) * 2),
                  Wsrc + (long)(colB + r) * lda + kcol + ck*8);
    }
    asm volatile("cp.async.commit_group;\n" ::);
}

template<int MT>
__device__ __forceinline__ void compute_tile(uint32_t aB, uint32_t bB, int lane,
                                             int wr0, int wc0, float acc[][4][4]) {
    #pragma unroll
    for (int kst = 0; kst < 2; kst++) {
        unsigned a[MT][4], b[4][2];
        int arow = wr0 + (lane & 15);
        int acol = kst*16 + (lane >> 4) * 8;
        #pragma unroll
        for (int i = 0; i < MT; i++)
            ldsm_x4(a[i], aB + (unsigned)(((arow + i*16) * 40 + acol) * 2));
        #pragma unroll
        for (int jj = 0; jj < 2; jj++) {
            unsigned t[4];
            int brow = wc0 + jj*16 + (lane & 7) + ((lane >> 4) & 1) * 8;
            int bcol = kst*16 + ((lane >> 3) & 1) * 8;
            ldsm_x4(t, bB + (unsigned)((brow * 40 + bcol) * 2));
            b[jj*2][0]   = t[0]; b[jj*2][1]   = t[1];
            b[jj*2+1][0] = t[2]; b[jj*2+1][1] = t[3];
        }
        #pragma unroll
        for (int i = 0; i < MT; i++)
            #pragma unroll
            for (int j = 0; j < 4; j++)
                mma_bf16(acc[i][j], a[i], b[j]);
    }
}

template<int MODE, int BM, bool GATHER>
__global__ void __launch_bounds__(256)
k_gemm(const __nv_bfloat16* __restrict__ A1, const __nv_bfloat16* __restrict__ A2,
       const __nv_bfloat16* __restrict__ Wa, const __nv_bfloat16* __restrict__ Wb,
       const float* __restrict__ biasA, const float* __restrict__ biasB,
       __nv_bfloat16* __restrict__ C,
       const __nv_bfloat16* __restrict__ rzb, const __nv_bfloat16* __restrict__ Hin,
       const int* __restrict__ tblA1, const int* __restrict__ cntPtr, int exitMode,
       int K1, int K2, int Nout) {
    constexpr int MT = BM / 32;       // warp m-tiles of 16
    extern __shared__ __nv_bfloat16 sm[];
    const int tid = threadIdx.x, lane = tid & 31, warp = tid >> 5;
    const int wr0 = (warp >> 2) * (BM/2), wc0 = (warp & 3) * 32;
    const long rowB = (long)blockIdx.x * BM;
    const int  colB = blockIdx.y * 128;

    int nk1 = K1 / 32;
    if (exitMode == 1) {
        if (rowB >= *cntPtr) return;                       // compact region only
    } else if (exitMode == 3) {
        if (rowB >= *cntPtr) nk1 = 0;                      // losers: skip gi half
    }

    uint32_t smBase = (uint32_t)__cvta_generic_to_shared(sm);
    const int asz = BM * 40, bsz = 128 * 40;      // elements per stage

    float acc[MT][4][4];
    float acc2[MT][4][4];
    #pragma unroll
    for (int i = 0; i < MT; i++)
        #pragma unroll
        for (int j = 0; j < 4; j++)
            #pragma unroll
            for (int e = 0; e < 4; e++) {
                acc[i][j][e] = 0.f;
                if (MODE == 3) acc2[i][j][e] = 0.f;
            }

    const int NK = nk1 + K2 / 32;     // always even (8/16/32)

    auto issue = [&](int k, int stage) {
        if (k < nk1)
            load_tile<BM, GATHER>(A1, tblA1, Wa, K1, k*32, rowB, colB, smBase,
                                  stage*asz, 4*asz + stage*bsz, tid);
        else
            load_tile<BM, false >(A2, nullptr, Wb, K2, (k - nk1)*32, rowB, colB, smBase,
                                  stage*asz, 4*asz + stage*bsz, tid);
    };

    // Prologue: groups 0,1 in stages 0,1.
    issue(0, 0); issue(1, 1);

    for (int kt = 0; kt < NK; kt += 2) {
        // All committed groups are exactly 0..kt+1 — wait for them all.
        asm volatile("cp.async.wait_group 0;\n" ::);
        __syncthreads();                  // releases stages (kt-2)&3, (kt-1)&3
        if (kt + 2 < NK) issue(kt + 2, (kt + 2) & 3);
        if (kt + 3 < NK) issue(kt + 3, (kt + 3) & 3);
        const int st0 = kt & 3, st1 = (kt + 1) & 3;
        uint32_t aB0 = smBase + (unsigned)((st0 * asz) * 2);
        uint32_t bB0 = smBase + (unsigned)((4*asz + st0 * bsz) * 2);
        uint32_t aB1 = smBase + (unsigned)((st1 * asz) * 2);
        uint32_t bB1 = smBase + (unsigned)((4*asz + st1 * bsz) * 2);
        if (MODE == 3 && kt >= nk1) {
            compute_tile<MT>(aB0, bB0, lane, wr0, wc0, acc2);
            compute_tile<MT>(aB1, bB1, lane, wr0, wc0, acc2);
        } else {
            compute_tile<MT>(aB0, bB0, lane, wr0, wc0, acc);
            compute_tile<MT>(aB1, bB1, lane, wr0, wc0, acc);
        }
    }

    const int laneR = lane >> 2, laneC = (lane & 3) * 2;
    #pragma unroll
    for (int i = 0; i < MT; i++) {
        #pragma unroll
        for (int e = 0; e < 2; e++) {
            long r = rowB + wr0 + i*16 + laneR + e*8;
            #pragma unroll
            for (int j = 0; j < 4; j++) {
                int c = colB + wc0 + j*8 + laneC;
                float v0 = acc[i][j][e*2], v1 = acc[i][j][e*2+1];
                if (MODE == 0) {
                    __nv_bfloat162 o;
                    o.x = __float2bfloat16_rn(geluf(v0 + biasA[c]));
                    o.y = __float2bfloat16_rn(geluf(v1 + biasA[c+1]));
                    *reinterpret_cast<__nv_bfloat162*>(C + r*Nout + c) = o;
                } else if (MODE == 1) {
                    __nv_bfloat162 o;
                    o.x = __float2bfloat16_rn(v0 + biasA[c]);
                    o.y = __float2bfloat16_rn(v1 + biasA[c+1]);
                    *reinterpret_cast<__nv_bfloat162*>(C + r*Nout + c) = o;
                } else if (MODE == 2) {
                    __nv_bfloat162 o;
                    o.x = __float2bfloat16_rn(sigmf(v0 + biasA[c]));
                    o.y = __float2bfloat16_rn(sigmf(v1 + biasA[c+1]));
                    *reinterpret_cast<__nv_bfloat162*>(C + r*Nout + c) = o;
                } else {
                    // i-gate half = acc (zero for loser blocks, nk1=0)
                    float i0 = v0 + biasA[c],            i1 = v1 + biasA[c+1];
                    float h0 = acc2[i][j][e*2] + biasB[c];
                    float h1 = acc2[i][j][e*2+1] + biasB[c+1];
                    float2 rr = __bfloat1622float2(*reinterpret_cast<const __nv_bfloat162*>(rzb + r*512 + c));
                    float2 zz = __bfloat1622float2(*reinterpret_cast<const __nv_bfloat162*>(rzb + r*512 + 256 + c));
                    float2 hh = __bfloat1622float2(*reinterpret_cast<const __nv_bfloat162*>(Hin + r*256 + c));
                    float n0 = tanhf(fmaf(rr.x, h0, i0));
                    float n1 = tanhf(fmaf(rr.y, h1, i1));
                    __nv_bfloat162 o;
                    o.x = __float2bfloat16_rn(fmaf(zz.x, hh.x - n0, n0));   // (1-z)n + zH
                    o.y = __float2bfloat16_rn(fmaf(zz.y, hh.y - n1, n1));
                    *reinterpret_cast<__nv_bfloat162*>(C + r*256 + c) = o;
                }
            }
        }
    }
}

// ---------------------------------------------------------------------------
// Final head (tiny, fp32).  Hfin is perm-layout; invp maps target -> perm row.
// ---------------------------------------------------------------------------
__global__ void k_combined(const __nv_bfloat16* __restrict__ Hfin, const int* __restrict__ s,
                           const int* __restrict__ kk, const float* __restrict__ emb,
                           const float* __restrict__ combW, const float* __restrict__ combB,
                           const int* __restrict__ invp) {
    __shared__ float x[2*DV];
    int b = blockIdx.x, t = threadIdx.x;
    int srow = s[b], krow = kk[b];
    int pos = invp[b * NV + srow];
    x[t]      = __bfloat162float(Hfin[(size_t)pos*DV + t]);
    x[DV + t] = emb[(size_t)krow*DV + t];
    __syncthreads();
    const float* w = combW + (size_t)t * (2*DV);
    float acc = combB[t];
    #pragma unroll 8
    for (int j = 0; j < 2*DV; j++) acc = fmaf(x[j], w[j], acc);
    g_comb[b*DV + t] = geluf(acc);
}

__global__ void k_logits(const float* __restrict__ headW, const float* __restrict__ headB,
                         float* __restrict__ out) {
    __shared__ float cb[BV*DV];
    for (int i = threadIdx.x; i < BV*DV; i += 256) cb[i] = g_comb[i];
    __syncthreads();
    int warp = threadIdx.x >> 5, lane = threadIdx.x & 31;
    int n = blockIdx.x * 8 + warp;                     // 512 blocks x 8 warps = 4096
    const float4* w4 = reinterpret_cast<const float4*>(headW + (size_t)n*DV);
    float acc[BV];
    #pragma unroll
    for (int b = 0; b < BV; b++) acc[b] = 0.f;
    #pragma unroll
    for (int c = lane; c < DV/4; c += 32) {
        float4 wv = w4[c];
        #pragma unroll
        for (int b = 0; b < BV; b++) {
            const float* cbb = &cb[b*DV + c*4];
            acc[b] += wv.x*cbb[0] + wv.y*cbb[1] + wv.z*cbb[2] + wv.w*cbb[3];
        }
    }
    #pragma unroll
    for (int off = 16; off; off >>= 1)
        #pragma unroll
        for (int b = 0; b < BV; b++)
            acc[b] += __shfl_down_sync(0xFFFFFFFFu, acc[b], off);
    if (lane == 0) {
        float hb = headB[n];
        #pragma unroll
        for (int b = 0; b < BV; b++) out[b*NV + n] = acc[b] + hb;
    }
}

// ---------------------------------------------------------------------------
// Host launcher
// ---------------------------------------------------------------------------
extern "C" void kernel_launch(void* const* d_in, const int* in_sizes, int n_in,
                              void* d_out, int out_size) {
    const int*   p     = (const int*)d_in[0];
    const int*   s     = (const int*)d_in[1];
    const int*   kk    = (const int*)d_in[2];
    const float* emb   = (const float*)d_in[3];
    const float* W1    = (const float*)d_in[4];
    const float* b1    = (const float*)d_in[5];
    const float* W2    = (const float*)d_in[6];
    const float* b2    = (const float*)d_in[7];
    const float* Wih   = (const float*)d_in[8];
    const float* Whh   = (const float*)d_in[9];
    const float* bih   = (const float*)d_in[10];
    const float* bhh   = (const float*)d_in[11];
    const float* combW = (const float*)d_in[12];
    const float* combB = (const float*)d_in[13];
    const float* headW = (const float*)d_in[14];
    const float* headB = (const float*)d_in[15];
    float* out = (float*)d_out;

    void *pH0, *pH1, *pHid, *pMsgs, *pRz, *pEmbf, *pW1, *pW2, *pWih, *pWhh, *pBrz;
    void *pRowsP, *pA1, *pA10, *pInvp, *pCnt;
    cudaGetSymbolAddress(&pH0,  g_H0);
    cudaGetSymbolAddress(&pH1,  g_H1);
    cudaGetSymbolAddress(&pHid, g_hid);
    cudaGetSymbolAddress(&pMsgs,g_msgs);
    cudaGetSymbolAddress(&pRz,  g_rz);
    cudaGetSymbolAddress(&pEmbf,g_embf);
    cudaGetSymbolAddress(&pW1,  g_W1);
    cudaGetSymbolAddress(&pW2,  g_W2);
    cudaGetSymbolAddress(&pWih, g_Wih);
    cudaGetSymbolAddress(&pWhh, g_Whh);
    cudaGetSymbolAddress(&pBrz, g_brz);
    cudaGetSymbolAddress(&pRowsP,g_rowsP);
    cudaGetSymbolAddress(&pA1,  g_a1idx);
    cudaGetSymbolAddress(&pA10, g_a1idx0);
    cudaGetSymbolAddress(&pInvp,g_invp);
    cudaGetSymbolAddress(&pCnt, g_cnt);

    const int SM128 = 4*(128*40 + 128*40) * 2;     // 81920 B
    const int SM64  = 4*(64*40  + 128*40) * 2;     // 61440 B
    cudaFuncSetAttribute((const void*)k_gemm<0,128,false>, cudaFuncAttributeMaxDynamicSharedMemorySize, SM128);
    cudaFuncSetAttribute((const void*)k_gemm<0,128,true >, cudaFuncAttributeMaxDynamicSharedMemorySize, SM128);
    cudaFuncSetAttribute((const void*)k_gemm<1,128,false>, cudaFuncAttributeMaxDynamicSharedMemorySize, SM128);
    cudaFuncSetAttribute((const void*)k_gemm<1,64 ,false>, cudaFuncAttributeMaxDynamicSharedMemorySize, SM64);
    cudaFuncSetAttribute((const void*)k_gemm<2,128,true >, cudaFuncAttributeMaxDynamicSharedMemorySize, SM128);
    cudaFuncSetAttribute((const void*)k_gemm<3,64 ,true >, cudaFuncAttributeMaxDynamicSharedMemorySize, SM64);

    const __nv_bfloat16* bW1  = (const __nv_bfloat16*)pW1;
    const __nv_bfloat16* bW2  = (const __nv_bfloat16*)pW2;
    const __nv_bfloat16* bWih = (const __nv_bfloat16*)pWih;
    const __nv_bfloat16* bWhh = (const __nv_bfloat16*)pWhh;
    __nv_bfloat16* Hc   = (__nv_bfloat16*)pH0;
    __nv_bfloat16* Hn   = (__nv_bfloat16*)pH1;
    __nv_bfloat16* msgs = (__nv_bfloat16*)pMsgs;
    __nv_bfloat16* rz   = (__nv_bfloat16*)pRz;
    __nv_bfloat16* hid  = (__nv_bfloat16*)pHid;
    const int* cntP = (const int*)pCnt;

    // Launch order keeps a GEMM at launch #4 (ncu capture point):
    // prep(1), win_fill(2), compact(3), L0-hid(4).
    k_prep<<<1024, 256>>>(W1, W2, Wih, Whh, bih, bhh, emb);
    k_win_fill<<<MV/256, 256>>>(p);
    k_compact<<<MV/256, 256>>>();

    // Layer 0 MLP on NV shared emb rows (dense)
    k_gemm<0,128,false><<<dim3(NV/128, 8), 256, SM128>>>(
        (__nv_bfloat16*)pEmbf, nullptr, bW1, nullptr, b1, nullptr, hid,
        nullptr, nullptr, nullptr, nullptr, 0, 256, 0, 1024);
    k_gemm<1,128,false><<<dim3(NV/128, 2), 256, SM128>>>(
        hid, nullptr, bW2, nullptr, b2, nullptr, msgs,
        nullptr, nullptr, nullptr, nullptr, 0, 1024, 0, 256);

    // Hp init + rowsP composition (needs compact)
    k_h0p<<<(MV*32)/256, 256>>>(emb);

    for (int l = 0; l < LV; l++) {
        const int* a1 = (l == 0) ? (const int*)pA10 : (const int*)pA1;
        if (l > 0) {
            // MLP only on winner rows (compact): A = Hp gathered via rowsP.
            k_gemm<0,128,true><<<dim3(MV/128, 8), 256, SM128>>>(
                Hc, nullptr, bW1, nullptr, b1, nullptr, hid,
                nullptr, nullptr, (const int*)pRowsP, cntP, 1, 256, 0, 1024);
            // msgs: BM=64 to fix wave quantization (324 -> ~648 active blocks).
            k_gemm<1,64,false><<<dim3(MV/64, 2), 256, SM64>>>(
                hid, nullptr, bW2, nullptr, b2, nullptr, msgs,
                nullptr, nullptr, nullptr, cntP, 1, 1024, 0, 256);
        }
        // rz: sigmoid(msgs[a1]@Wih_rz^T + Hp@Whh_rz^T + brz), perm-dense.
        // Dynamic-K: loser blocks skip the gi half entirely (nk1=0).
        k_gemm<2,128,true><<<dim3(MV/128, 4), 256, SM128>>>(
            msgs, Hc, bWih, bWhh, (float*)pBrz, nullptr, rz,
            nullptr, nullptr, a1, cntP, 3, 256, 256, 512);
        // n-gate + GRU update -> Hn (perm-dense), dynamic-K likewise.
        k_gemm<3,64,true><<<dim3(MV/64, 2), 256, SM64>>>(
            msgs, Hc, bWih + 512*DV, bWhh + 512*DV, bih + 512, bhh + 512, Hn,
            rz, Hc, a1, cntP, 3, 256, 256, 256);
        __nv_bfloat16* t = Hc; Hc = Hn; Hn = t;
    }

    k_combined<<<BV, 256>>>(Hc, s, kk, emb, combW, combB, (const int*)pInvp);
    k_logits<<<NV/8, 256>>>(headW, headB, out);
}